// round 10
// baseline (speedup 1.0000x reference)
#include <cuda_runtime.h>
#include <cstdint>
#include <math.h>

#define HW      262144
#define NB      8
#define NC      16
#define NBC     128                // class-planes
#define KB      16384              // uniform z-buckets over (-4, 4)
#define THREADS 1024
#define BPT     (KB / THREADS)     // 16 e-buckets per thread
#define DYN_SMEM (2 * KB * 4)      // dual histogram copies = 128 KB

// Scratch (no allocations allowed)
__device__ unsigned char g_labels[NB * HW];
__device__ double        g_part[NBC * 2];
__device__ unsigned int  g_arrive;          // zero-init; reset by combiner each call

// K0: target (int32 or int64) -> uint8. Dtype detected per-block (uniform branch).
__global__ __launch_bounds__(1024) void prep_kernel(const void* __restrict__ target) {
    __shared__ int s_is32;
    if (threadIdx.x < 32) {
        const unsigned long long* t64 = (const unsigned long long*)target;
        unsigned hi = (unsigned)(t64[threadIdx.x] >> 32) |
                      (unsigned)(t64[threadIdx.x + 32] >> 32);
        #pragma unroll
        for (int off = 16; off > 0; off >>= 1)
            hi |= __shfl_down_sync(0xFFFFFFFFu, hi, off);
        if (threadIdx.x == 0) s_is32 = (hi != 0);
    }
    __syncthreads();
    const int is32 = s_is32;

    int q = blockIdx.x * blockDim.x + threadIdx.x;
    if (q < (NB * HW) / 4) {
        uchar4 o;
        if (is32) {
            int4 v = ((const int4*)target)[q];
            o.x = (unsigned char)v.x; o.y = (unsigned char)v.y;
            o.z = (unsigned char)v.z; o.w = (unsigned char)v.w;
        } else {
            longlong2 a = ((const longlong2*)target)[2 * q];
            longlong2 b = ((const longlong2*)target)[2 * q + 1];
            o.x = (unsigned char)a.x; o.y = (unsigned char)a.y;
            o.z = (unsigned char)b.x; o.w = (unsigned char)b.y;
        }
        ((uchar4*)g_labels)[q] = o;
    }
}

// K1: one block per plane (R5-proven skeleton). Hot loop has ZERO transcendentals:
// key = uniform z-bucket; one smem atomic into a warp-parity-private copy.
// hist packs n(16b)|pos(8b)|ign(8b). Cold phase: merge copies, map buckets to
// descending-e order (neg at bucket j: e=1+tanh(z_j); pos mirrored at KB-1-j),
// per-bucket exact-double e and BCE=softplus(z), suffix scan, exact-integer
// Jaccard integral, non-spinning last-block ticket combine.
__global__ __launch_bounds__(THREADS, 1) void lovasz_kernel(const float* __restrict__ logits,
                                                            float* __restrict__ out) {
    extern __shared__ unsigned int hist[];            // 2*KB entries (dual copies)
    __shared__ unsigned long long sbuf[THREADS];
    __shared__ double             wsum[32][2];
    __shared__ double             fin[NBC][2];
    __shared__ unsigned           s_rank;

    const int bc  = blockIdx.x;
    const int b   = bc >> 4;
    const int c   = bc & 15;
    const int tid = threadIdx.x;

    for (int j = tid; j < 2 * KB; j += THREADS) hist[j] = 0u;
    __syncthreads();

    const float4* lg4 = reinterpret_cast<const float4*>(logits + (size_t)bc * HW);
    const uchar4* lb4 = reinterpret_cast<const uchar4*>(g_labels + (size_t)b * HW);
    unsigned int* myhist = hist + (((tid >> 5) & 1) ? KB : 0);

    #pragma unroll 4
    for (int q = tid; q < HW / 4; q += THREADS) {
        float4 z4 = lg4[q];
        uchar4 t4 = lb4[q];
        float zz[4] = { z4.x, z4.y, z4.z, z4.w };
        int   tt[4] = { t4.x, t4.y, t4.z, t4.w };
        #pragma unroll
        for (int j = 0; j < 4; j++) {
            int key = (int)fmaf(zz[j], 2048.0f, 8192.0f);   // z*KB/8 + KB/2
            key = min(max(key, 0), KB - 1);
            int t = tt[j];
            unsigned inc = 1u + ((t == c) ? 0x10000u : 0u) + ((unsigned)(t >> 4) << 24);
            atomicAdd(myhist + key, inc);
        }
    }
    __syncthreads();

    // Merge dual copies (packed add; fields can't overflow).
    for (int j = tid; j < KB; j += THREADS) hist[j] += hist[j + KB];
    __syncthreads();

    // Per-thread e-bucket totals (counts only).
    unsigned n_t = 0, p_t = 0;
    const int lo = tid * BPT;
    #pragma unroll
    for (int j = 0; j < BPT; j++) {
        const int eb = lo + j;
        unsigned va = hist[eb];
        unsigned vb = hist[KB - 1 - eb];
        n_t += (va & 0xFFFFu) - ((va >> 16) & 0xFFu) + ((vb >> 16) & 0xFFu);
        p_t += (vb >> 16) & 0xFFu;
    }
    sbuf[tid] = ((unsigned long long)n_t << 32) | (unsigned long long)p_t;
    __syncthreads();
    // Inclusive SUFFIX scan (descending-error order).
    for (int d = 1; d < THREADS; d <<= 1) {
        unsigned long long v = (tid + d < THREADS) ? sbuf[tid + d] : 0ULL;
        __syncthreads();
        sbuf[tid] += v;
        __syncthreads();
    }
    const unsigned long long tot = sbuf[0];
    const long long P = (long long)(tot & 0xFFFFFFFFULL);
    unsigned long long inc2 = sbuf[tid];
    long long i0 = (long long)(inc2 >> 32) - (long long)n_t;
    long long p0 = (long long)(inc2 & 0xFFFFFFFFULL) - (long long)p_t;

    // Single walk high->low: exact-double per-bucket e & BCE + exact-integer Jaccard.
    double contrib = 0.0, bced = 0.0;
    const double dz = 8.0 / (double)KB;   // z-bucket width
    #pragma unroll
    for (int j = BPT - 1; j >= 0; j--) {
        const int eb = lo + j;
        unsigned va = hist[eb];
        unsigned vb = hist[KB - 1 - eb];
        if ((va | vb) == 0u) continue;
        long long pA = (long long)((va >> 16) & 0xFFu);
        long long iA = (long long)(va >> 24);
        long long pB = (long long)((vb >> 16) & 0xFFu);
        long long n  = (long long)(va & 0xFFFFu) - pA + pB;

        double zm = ((double)eb + 0.5) * dz - 4.0;   // bucket-mid z (negatives side)
        double u  = exp(zm);
        double u2 = u * u;
        double e  = 2.0 * u2 / (u2 + 1.0);           // 1 + tanh(zm), exact
        double gb = log1p(u);                        // softplus(zm) = per-bucket BCE
        bced += (double)((long long)(va & 0xFFFFu) - pA - iA + pB) * gb;

        if (n > 0) {
            long long i1 = i0 + n, p1 = p0 + pB;
            double dJ;
            if (P > 0) {
                long long A0 = P - p0, B0 = P + i0 - p0;
                long long A1 = P - p1, B1 = P + i1 - p1;
                dJ = (double)(A0 * B1 - A1 * B0) / ((double)B0 * (double)B1);
            } else {
                dJ = (i0 == 0) ? 1.0 : 0.0;
            }
            contrib += e * dJ;
            i0 = i1; p0 = p1;
        }
    }

    // Deterministic block reduction.
    const unsigned mask = 0xFFFFFFFFu;
    #pragma unroll
    for (int off = 16; off > 0; off >>= 1) {
        contrib += __shfl_down_sync(mask, contrib, off);
        bced    += __shfl_down_sync(mask, bced, off);
    }
    const int wid = tid >> 5, lane = tid & 31;
    if (lane == 0) { wsum[wid][0] = contrib; wsum[wid][1] = bced; }
    __syncthreads();
    if (wid == 0) {
        double cv = wsum[lane][0];
        double bv = wsum[lane][1];
        #pragma unroll
        for (int off = 16; off > 0; off >>= 1) {
            cv += __shfl_down_sync(mask, cv, off);
            bv += __shfl_down_sync(mask, bv, off);
        }
        if (lane == 0) { g_part[bc * 2 + 0] = cv; g_part[bc * 2 + 1] = bv; }
    }

    // Non-spinning last-arriving-block combine (R3/R4/R5-proven; cannot deadlock).
    __threadfence();
    __syncthreads();
    if (tid == 0) s_rank = atomicAdd(&g_arrive, 1u);
    __syncthreads();
    if (s_rank == NBC - 1) {
        __threadfence();
        if (tid < NBC) {
            fin[tid][0] = __ldcg(&g_part[tid * 2]);
            fin[tid][1] = __ldcg(&g_part[tid * 2 + 1]);
        }
        __syncthreads();
        for (int stride = NBC / 2; stride > 0; stride >>= 1) {
            if (tid < stride) {
                fin[tid][0] += fin[tid + stride][0];
                fin[tid][1] += fin[tid + stride][1];
            }
            __syncthreads();
        }
        if (tid == 0) {
            out[0] = (float)(fin[0][0] * (1.0 / 128.0) + fin[0][1] * (1.0 / 33554432.0));
            g_arrive = 0;
        }
    }
}

extern "C" void kernel_launch(void* const* d_in, const int* in_sizes, int n_in,
                              void* d_out, int out_size) {
    const float* logits;
    const void*  target;
    if (in_sizes[0] == NB * NC * HW) {
        logits = (const float*)d_in[0];
        target = d_in[1];
    } else {
        logits = (const float*)d_in[1];
        target = d_in[0];
    }
    cudaFuncSetAttribute(lovasz_kernel, cudaFuncAttributeMaxDynamicSharedMemorySize, DYN_SMEM);
    prep_kernel<<<(NB * HW / 4 + 1023) / 1024, 1024>>>(target);
    lovasz_kernel<<<NBC, THREADS, DYN_SMEM>>>(logits, (float*)d_out);
}

// round 11
// speedup vs baseline: 1.3071x; 1.3071x over previous
#include <cuda_runtime.h>
#include <cstdint>

#define HW      262144
#define NB      8
#define NC      16
#define NBC     128                // class-planes
#define KB      8192               // buckets over x=tanh(z) in (-1,1)
#define THREADS 1024
#define BPT     (KB / THREADS)     // 8 e-buckets per thread
#define DYN_SMEM (2 * KB * 4)      // dual histogram copies = 64 KB

// Scratch (no allocations allowed)
__device__ unsigned char g_labels[NB * HW];
__device__ double        g_part[NBC * 2];
__device__ unsigned int  g_arrive;          // zero-init; reset by combiner each call

__device__ __forceinline__ float fast_tanh(float x) { float y; asm("tanh.approx.f32 %0, %1;" : "=f"(y) : "f"(x)); return y; }
__device__ __forceinline__ float fast_lg2(float x)  { float y; asm("lg2.approx.f32 %0, %1;"  : "=f"(y) : "f"(x)); return y; }
__device__ __forceinline__ float fast_rcp(float x)  { float y; asm("rcp.approx.f32 %0, %1;"  : "=f"(y) : "f"(x)); return y; }

// K0: target (int32 or int64) -> uint8, 16 labels per thread.
// Dtype detected per-block: read first 64 values as int64; if truly int64 all
// high words are 0 (labels 0..16); if int32 the OR of "high words" is nonzero.
__global__ __launch_bounds__(1024) void prep_kernel(const void* __restrict__ target) {
    __shared__ int s_is32;
    if (threadIdx.x < 32) {
        const unsigned long long* t64 = (const unsigned long long*)target;
        unsigned hi = (unsigned)(t64[threadIdx.x] >> 32) |
                      (unsigned)(t64[threadIdx.x + 32] >> 32);
        #pragma unroll
        for (int off = 16; off > 0; off >>= 1)
            hi |= __shfl_down_sync(0xFFFFFFFFu, hi, off);
        if (threadIdx.x == 0) s_is32 = (hi != 0);
    }
    __syncthreads();
    const int is32 = s_is32;

    int q = blockIdx.x * blockDim.x + threadIdx.x;   // 16-label group
    if (q < (NB * HW) / 16) {
        uint4 o;
        unsigned w[4];
        if (is32) {
            const int4* p = (const int4*)target + (size_t)q * 4;
            #pragma unroll
            for (int k = 0; k < 4; k++) {
                int4 v = p[k];
                w[k] = (unsigned)v.x | ((unsigned)v.y << 8) |
                       ((unsigned)v.z << 16) | ((unsigned)v.w << 24);
            }
        } else {
            const longlong2* p = (const longlong2*)target + (size_t)q * 8;
            #pragma unroll
            for (int k = 0; k < 4; k++) {
                longlong2 a = p[2 * k];
                longlong2 b = p[2 * k + 1];
                w[k] = (unsigned)(a.x & 0xFF) | ((unsigned)(a.y & 0xFF) << 8) |
                       ((unsigned)(b.x & 0xFF) << 16) | ((unsigned)(b.y & 0xFF) << 24);
            }
        }
        o.x = w[0]; o.y = w[1]; o.z = w[2]; o.w = w[3];
        ((uint4*)g_labels)[q] = o;
    }
}

// K1: one block per plane (R5 structure, measured 43us). Hot loop: tanh -> x-key
// -> one smem atomic into warp-parity copy. hist packs n(16b)|pos(8b)|ign(8b).
// Cold phase: merge copies; e-bucket mapping (neg at j: e=1+x_j; pos mirrored at
// KB-1-j: e=1-x_j); per-bucket BCE via log1p(sqrt(e/(2-e))); suffix scan; exact
// integer Jaccard integral; non-spinning last-block ticket combine.
__global__ __launch_bounds__(THREADS, 1) void lovasz_kernel(const float* __restrict__ logits,
                                                            float* __restrict__ out) {
    extern __shared__ unsigned int hist[];            // 2*KB entries (dual copies)
    __shared__ unsigned long long sbuf[THREADS];
    __shared__ double             wsum[32][2];
    __shared__ double             fin[NBC][2];
    __shared__ unsigned           s_rank;

    const int bc  = blockIdx.x;
    const int b   = bc >> 4;
    const int c   = bc & 15;
    const int tid = threadIdx.x;

    for (int j = tid; j < 2 * KB; j += THREADS) hist[j] = 0u;
    __syncthreads();

    const float4* lg4 = reinterpret_cast<const float4*>(logits + (size_t)bc * HW);
    const uint2*  lb8 = reinterpret_cast<const uint2*>(g_labels + (size_t)b * HW);
    unsigned int* myhist = hist + (((tid >> 5) & 1) ? KB : 0);

    #pragma unroll 2
    for (int q = tid; q < HW / 8; q += THREADS) {
        float4 zA = lg4[2 * q];
        float4 zB = lg4[2 * q + 1];
        uint2  lb = lb8[q];
        float zz[8] = { zA.x, zA.y, zA.z, zA.w, zB.x, zB.y, zB.z, zB.w };
        unsigned tw[8];
        #pragma unroll
        for (int j = 0; j < 4; j++) {
            tw[j]     = (lb.x >> (8 * j)) & 0xFFu;
            tw[j + 4] = (lb.y >> (8 * j)) & 0xFFu;
        }
        #pragma unroll
        for (int j = 0; j < 8; j++) {
            float x = fast_tanh(zz[j]);
            int key = (int)fmaf(x, (float)(KB / 2), (float)(KB / 2));
            key = min(key, KB - 1);
            unsigned t = tw[j];
            unsigned inc = 1u + ((t == (unsigned)c) ? 0x10000u : 0u)
                              + ((t & 16u) << 20);
            atomicAdd(myhist + key, inc);
        }
    }
    __syncthreads();

    // Merge dual copies (packed add; fields can't overflow).
    for (int j = tid; j < KB; j += THREADS) hist[j] += hist[j + KB];
    __syncthreads();

    // Per-thread e-bucket totals + per-bucket BCE (float fast-math, R5 form).
    unsigned n_t = 0, p_t = 0;
    double bced = 0.0;
    const int lo = tid * BPT;
    const float LN2 = 0.6931471805599453f;
    #pragma unroll
    for (int j = 0; j < BPT; j++) {
        const int eb = lo + j;
        unsigned va = hist[eb];
        unsigned vb = hist[KB - 1 - eb];
        unsigned nA = va & 0xFFFFu;
        unsigned pA = (va >> 16) & 0xFFu;
        unsigned iA = va >> 24;
        unsigned pB = (vb >> 16) & 0xFFu;
        n_t += nA - pA + pB;
        p_t += pB;
        float em = ((float)eb + 0.5f) * (2.0f / (float)KB);
        float s  = sqrtf(em * fast_rcp(2.0f - em));
        float gb = fast_lg2(1.0f + s) * LN2;
        bced += (double)(nA - pA - iA + pB) * (double)gb;
    }
    sbuf[tid] = ((unsigned long long)n_t << 32) | (unsigned long long)p_t;
    __syncthreads();
    // Inclusive SUFFIX scan (descending-error order).
    for (int d = 1; d < THREADS; d <<= 1) {
        unsigned long long v = (tid + d < THREADS) ? sbuf[tid + d] : 0ULL;
        __syncthreads();
        sbuf[tid] += v;
        __syncthreads();
    }
    const unsigned long long tot = sbuf[0];
    const long long P = (long long)(tot & 0xFFFFFFFFULL);
    unsigned long long inc2 = sbuf[tid];
    long long i0 = (long long)(inc2 >> 32) - (long long)n_t;
    long long p0 = (long long)(inc2 & 0xFFFFFFFFULL) - (long long)p_t;

    // Walk e-buckets high->low; exact integer Jaccard deltas.
    double contrib = 0.0;
    const double de = 2.0 / (double)KB;
    #pragma unroll
    for (int j = BPT - 1; j >= 0; j--) {
        const int eb = lo + j;
        unsigned va = hist[eb];
        unsigned vb = hist[KB - 1 - eb];
        long long p = (long long)((vb >> 16) & 0xFFu);
        long long n = (long long)(va & 0xFFFFu) - (long long)((va >> 16) & 0xFFu) + p;
        if (n > 0) {
            long long i1 = i0 + n, p1 = p0 + p;
            double dJ;
            if (P > 0) {
                long long A0 = P - p0, B0 = P + i0 - p0;
                long long A1 = P - p1, B1 = P + i1 - p1;
                dJ = (double)(A0 * B1 - A1 * B0) / ((double)B0 * (double)B1);
            } else {
                dJ = (i0 == 0) ? 1.0 : 0.0;
            }
            contrib += ((double)eb + 0.5) * de * dJ;
            i0 = i1; p0 = p1;
        }
    }

    // Deterministic block reduction.
    const unsigned mask = 0xFFFFFFFFu;
    #pragma unroll
    for (int off = 16; off > 0; off >>= 1) {
        contrib += __shfl_down_sync(mask, contrib, off);
        bced    += __shfl_down_sync(mask, bced, off);
    }
    const int wid = tid >> 5, lane = tid & 31;
    if (lane == 0) { wsum[wid][0] = contrib; wsum[wid][1] = bced; }
    __syncthreads();
    if (wid == 0) {
        double cv = wsum[lane][0];
        double bv = wsum[lane][1];
        #pragma unroll
        for (int off = 16; off > 0; off >>= 1) {
            cv += __shfl_down_sync(mask, cv, off);
            bv += __shfl_down_sync(mask, bv, off);
        }
        if (lane == 0) { g_part[bc * 2 + 0] = cv; g_part[bc * 2 + 1] = bv; }
    }

    // Non-spinning last-arriving-block combine (proven R3-R5; cannot deadlock).
    __threadfence();
    __syncthreads();
    if (tid == 0) s_rank = atomicAdd(&g_arrive, 1u);
    __syncthreads();
    if (s_rank == NBC - 1) {
        __threadfence();
        if (tid < NBC) {
            fin[tid][0] = __ldcg(&g_part[tid * 2]);
            fin[tid][1] = __ldcg(&g_part[tid * 2 + 1]);
        }
        __syncthreads();
        for (int stride = NBC / 2; stride > 0; stride >>= 1) {
            if (tid < stride) {
                fin[tid][0] += fin[tid + stride][0];
                fin[tid][1] += fin[tid + stride][1];
            }
            __syncthreads();
        }
        if (tid == 0) {
            out[0] = (float)(fin[0][0] * (1.0 / 128.0) + fin[0][1] * (1.0 / 33554432.0));
            g_arrive = 0;
        }
    }
}

extern "C" void kernel_launch(void* const* d_in, const int* in_sizes, int n_in,
                              void* d_out, int out_size) {
    const float* logits;
    const void*  target;
    if (in_sizes[0] == NB * NC * HW) {
        logits = (const float*)d_in[0];
        target = d_in[1];
    } else {
        logits = (const float*)d_in[1];
        target = d_in[0];
    }
    cudaFuncSetAttribute(lovasz_kernel, cudaFuncAttributeMaxDynamicSharedMemorySize, DYN_SMEM);
    prep_kernel<<<(NB * HW / 16 + 1023) / 1024, 1024>>>(target);
    lovasz_kernel<<<NBC, THREADS, DYN_SMEM>>>(logits, (float*)d_out);
}

// round 12
// speedup vs baseline: 1.3665x; 1.0455x over previous
#include <cuda_runtime.h>
#include <cstdint>

#define HW      262144
#define NB      8
#define NC      16
#define NBC     128                // class-planes
#define KB      1024               // buckets over x=tanh(z) in (-1,1)
#define THREADS 1024
#define DYN_SMEM (KB * 32 * 4)     // lane-sliced histogram = 128 KB

// Scratch (no allocations allowed)
__device__ unsigned char g_labels[NB * HW];
__device__ double        g_part[NBC * 2];
__device__ unsigned int  g_arrive;          // zero-init; reset by combiner each call

__device__ __forceinline__ float fast_tanh(float x) { float y; asm("tanh.approx.f32 %0, %1;" : "=f"(y) : "f"(x)); return y; }
__device__ __forceinline__ float fast_lg2(float x)  { float y; asm("lg2.approx.f32 %0, %1;"  : "=f"(y) : "f"(x)); return y; }
__device__ __forceinline__ float fast_rcp(float x)  { float y; asm("rcp.approx.f32 %0, %1;"  : "=f"(y) : "f"(x)); return y; }

// K0: target (int32 or int64) -> uint8, 16 labels per thread. Dtype detected
// per-block: if truly int64 all high words are 0 (labels 0..16).
__global__ __launch_bounds__(1024) void prep_kernel(const void* __restrict__ target) {
    __shared__ int s_is32;
    if (threadIdx.x < 32) {
        const unsigned long long* t64 = (const unsigned long long*)target;
        unsigned hi = (unsigned)(t64[threadIdx.x] >> 32) |
                      (unsigned)(t64[threadIdx.x + 32] >> 32);
        #pragma unroll
        for (int off = 16; off > 0; off >>= 1)
            hi |= __shfl_down_sync(0xFFFFFFFFu, hi, off);
        if (threadIdx.x == 0) s_is32 = (hi != 0);
    }
    __syncthreads();
    const int is32 = s_is32;

    int q = blockIdx.x * blockDim.x + threadIdx.x;   // 16-label group
    if (q < (NB * HW) / 16) {
        uint4 o;
        unsigned w[4];
        if (is32) {
            const int4* p = (const int4*)target + (size_t)q * 4;
            #pragma unroll
            for (int k = 0; k < 4; k++) {
                int4 v = p[k];
                w[k] = (unsigned)v.x | ((unsigned)v.y << 8) |
                       ((unsigned)v.z << 16) | ((unsigned)v.w << 24);
            }
        } else {
            const longlong2* p = (const longlong2*)target + (size_t)q * 8;
            #pragma unroll
            for (int k = 0; k < 4; k++) {
                longlong2 a = p[2 * k];
                longlong2 b = p[2 * k + 1];
                w[k] = (unsigned)(a.x & 0xFF) | ((unsigned)(a.y & 0xFF) << 8) |
                       ((unsigned)(b.x & 0xFF) << 16) | ((unsigned)(b.y & 0xFF) << 24);
            }
        }
        o.x = w[0]; o.y = w[1]; o.z = w[2]; o.w = w[3];
        ((uint4*)g_labels)[q] = o;
    }
}

// K1: one block per plane. Lane-sliced histogram: cell = hist[key*32 + lane],
// bank == lane for every access -> guaranteed conflict-free smem atomics.
// Packed n(16b)|pos(8b)|ign(8b). Cold phase: 32-cell merge per bucket, e-bucket
// mapping (neg at j: e=1+x_j; pos mirrored at KB-1-j: e=1-x_j), per-bucket BCE
// via log1p(sqrt(e/(2-e))), suffix scan, exact-integer Jaccard integral,
// non-spinning last-block ticket combine.
__global__ __launch_bounds__(THREADS, 1) void lovasz_kernel(const float* __restrict__ logits,
                                                            float* __restrict__ out) {
    extern __shared__ unsigned int hist[];            // KB*32 cells
    __shared__ double   wsum[32][2];
    __shared__ double   fin[NBC][2];
    __shared__ unsigned s_rank;

    const int bc   = blockIdx.x;
    const int b    = bc >> 4;
    const int c    = bc & 15;
    const int tid  = threadIdx.x;
    const int lane = tid & 31;

    for (int j = tid; j < KB * 32; j += THREADS) hist[j] = 0u;
    __syncthreads();

    const float4* lg4 = reinterpret_cast<const float4*>(logits + (size_t)bc * HW);
    const uint2*  lb8 = reinterpret_cast<const uint2*>(g_labels + (size_t)b * HW);
    unsigned int* myslot = hist + lane;   // per-lane column; index step = key*32

    #pragma unroll 2
    for (int q = tid; q < HW / 8; q += THREADS) {
        float4 zA = lg4[2 * q];
        float4 zB = lg4[2 * q + 1];
        uint2  lb = lb8[q];
        float zz[8] = { zA.x, zA.y, zA.z, zA.w, zB.x, zB.y, zB.z, zB.w };
        unsigned tw[8];
        #pragma unroll
        for (int j = 0; j < 4; j++) {
            tw[j]     = (lb.x >> (8 * j)) & 0xFFu;
            tw[j + 4] = (lb.y >> (8 * j)) & 0xFFu;
        }
        #pragma unroll
        for (int j = 0; j < 8; j++) {
            float x = fast_tanh(zz[j]);
            int key = (int)fmaf(x, (float)(KB / 2), (float)(KB / 2));
            key = min(max(key, 0), KB - 1);
            unsigned t = tw[j];
            unsigned inc = 1u + ((t == (unsigned)c) ? 0x10000u : 0u)
                              + ((t & 16u) << 20);
            atomicAdd(myslot + (key << 5), inc);
        }
    }
    __syncthreads();

    // Merge 32 lane-cells per bucket (thread tid owns x-bucket tid; KB==THREADS).
    unsigned vm = 0;
    #pragma unroll
    for (int l = 0; l < 32; l++) vm += hist[(tid << 5) + l];  // packed add, no overflow
    __syncthreads();
    hist[tid] = vm;                       // merged hist now in hist[0..KB)
    __syncthreads();

    unsigned long long* sbuf = (unsigned long long*)(hist + 8192);  // scratch past merged region

    // Per-thread e-bucket totals + per-bucket BCE (1 e-bucket per thread).
    const int eb = tid;
    unsigned va = hist[eb];
    unsigned vb = hist[KB - 1 - eb];
    unsigned nA = va & 0xFFFFu;
    unsigned pA = (va >> 16) & 0xFFu;
    unsigned iA = va >> 24;
    unsigned pB = (vb >> 16) & 0xFFu;
    const unsigned n_t = nA - pA + pB;
    const unsigned p_t = pB;
    double bced;
    {
        const float LN2 = 0.6931471805599453f;
        float em = ((float)eb + 0.5f) * (2.0f / (float)KB);
        float s  = sqrtf(em * fast_rcp(2.0f - em));
        float gb = fast_lg2(1.0f + s) * LN2;
        bced = (double)(nA - pA - iA + pB) * (double)gb;
    }
    sbuf[tid] = ((unsigned long long)n_t << 32) | (unsigned long long)p_t;
    __syncthreads();
    // Inclusive SUFFIX scan (descending-error order).
    for (int d = 1; d < THREADS; d <<= 1) {
        unsigned long long v = (tid + d < THREADS) ? sbuf[tid + d] : 0ULL;
        __syncthreads();
        sbuf[tid] += v;
        __syncthreads();
    }
    const unsigned long long tot = sbuf[0];
    const long long P = (long long)(tot & 0xFFFFFFFFULL);
    unsigned long long inc2 = sbuf[tid];
    long long i0 = (long long)(inc2 >> 32) - (long long)n_t;
    long long p0 = (long long)(inc2 & 0xFFFFFFFFULL) - (long long)p_t;

    // Exact integer Jaccard delta for this e-bucket.
    double contrib = 0.0;
    {
        long long p = (long long)pB;
        long long n = (long long)n_t;
        if (n > 0) {
            long long i1 = i0 + n, p1 = p0 + p;
            double dJ;
            if (P > 0) {
                long long A0 = P - p0, B0 = P + i0 - p0;
                long long A1 = P - p1, B1 = P + i1 - p1;
                dJ = (double)(A0 * B1 - A1 * B0) / ((double)B0 * (double)B1);
            } else {
                dJ = (i0 == 0) ? 1.0 : 0.0;
            }
            contrib = ((double)eb + 0.5) * (2.0 / (double)KB) * dJ;
        }
    }

    // Deterministic block reduction.
    const unsigned mask = 0xFFFFFFFFu;
    #pragma unroll
    for (int off = 16; off > 0; off >>= 1) {
        contrib += __shfl_down_sync(mask, contrib, off);
        bced    += __shfl_down_sync(mask, bced, off);
    }
    const int wid = tid >> 5;
    if (lane == 0) { wsum[wid][0] = contrib; wsum[wid][1] = bced; }
    __syncthreads();
    if (wid == 0) {
        double cv = wsum[lane][0];
        double bv = wsum[lane][1];
        #pragma unroll
        for (int off = 16; off > 0; off >>= 1) {
            cv += __shfl_down_sync(mask, cv, off);
            bv += __shfl_down_sync(mask, bv, off);
        }
        if (lane == 0) { g_part[bc * 2 + 0] = cv; g_part[bc * 2 + 1] = bv; }
    }

    // Non-spinning last-arriving-block combine (proven R3-R10; cannot deadlock).
    __threadfence();
    __syncthreads();
    if (tid == 0) s_rank = atomicAdd(&g_arrive, 1u);
    __syncthreads();
    if (s_rank == NBC - 1) {
        __threadfence();
        if (tid < NBC) {
            fin[tid][0] = __ldcg(&g_part[tid * 2]);
            fin[tid][1] = __ldcg(&g_part[tid * 2 + 1]);
        }
        __syncthreads();
        for (int stride = NBC / 2; stride > 0; stride >>= 1) {
            if (tid < stride) {
                fin[tid][0] += fin[tid + stride][0];
                fin[tid][1] += fin[tid + stride][1];
            }
            __syncthreads();
        }
        if (tid == 0) {
            out[0] = (float)(fin[0][0] * (1.0 / 128.0) + fin[0][1] * (1.0 / 33554432.0));
            g_arrive = 0;
        }
    }
}

extern "C" void kernel_launch(void* const* d_in, const int* in_sizes, int n_in,
                              void* d_out, int out_size) {
    const float* logits;
    const void*  target;
    if (in_sizes[0] == NB * NC * HW) {
        logits = (const float*)d_in[0];
        target = d_in[1];
    } else {
        logits = (const float*)d_in[1];
        target = d_in[0];
    }
    cudaFuncSetAttribute(lovasz_kernel, cudaFuncAttributeMaxDynamicSharedMemorySize, DYN_SMEM);
    prep_kernel<<<(NB * HW / 16 + 1023) / 1024, 1024>>>(target);
    lovasz_kernel<<<NBC, THREADS, DYN_SMEM>>>(logits, (float*)d_out);
}

// round 13
// speedup vs baseline: 1.4915x; 1.0915x over previous
#include <cuda_runtime.h>
#include <cstdint>

#define HW      262144
#define NB      8
#define NC      16
#define NBC     128                // class-planes
#define KB      1024               // buckets over x=tanh(z) in (-1,1)
#define THREADS 1024
#define DYN_SMEM (KB * 32 * 4)     // lane-sliced histogram = 128 KB

// Scratch (no allocations allowed)
__device__ unsigned char g_labels[NB * HW];
__device__ double        g_part[NBC * 2];
__device__ unsigned int  g_arrive;          // zero-init; reset by combiner each call

__device__ __forceinline__ float fast_tanh(float x) { float y; asm("tanh.approx.f32 %0, %1;" : "=f"(y) : "f"(x)); return y; }
__device__ __forceinline__ float fast_lg2(float x)  { float y; asm("lg2.approx.f32 %0, %1;"  : "=f"(y) : "f"(x)); return y; }
__device__ __forceinline__ float fast_rcp(float x)  { float y; asm("rcp.approx.f32 %0, %1;"  : "=f"(y) : "f"(x)); return y; }

// K0: target (int32 or int64) -> uint8, 16 labels per thread. Dtype detected
// per-block: if truly int64 all high words are 0 (labels 0..16).
__global__ __launch_bounds__(1024) void prep_kernel(const void* __restrict__ target) {
    __shared__ int s_is32;
    if (threadIdx.x < 32) {
        const unsigned long long* t64 = (const unsigned long long*)target;
        unsigned hi = (unsigned)(t64[threadIdx.x] >> 32) |
                      (unsigned)(t64[threadIdx.x + 32] >> 32);
        #pragma unroll
        for (int off = 16; off > 0; off >>= 1)
            hi |= __shfl_down_sync(0xFFFFFFFFu, hi, off);
        if (threadIdx.x == 0) s_is32 = (hi != 0);
    }
    __syncthreads();
    const int is32 = s_is32;

    int q = blockIdx.x * blockDim.x + threadIdx.x;   // 16-label group
    if (q < (NB * HW) / 16) {
        uint4 o;
        unsigned w[4];
        if (is32) {
            const int4* p = (const int4*)target + (size_t)q * 4;
            #pragma unroll
            for (int k = 0; k < 4; k++) {
                int4 v = p[k];
                w[k] = (unsigned)v.x | ((unsigned)v.y << 8) |
                       ((unsigned)v.z << 16) | ((unsigned)v.w << 24);
            }
        } else {
            const longlong2* p = (const longlong2*)target + (size_t)q * 8;
            #pragma unroll
            for (int k = 0; k < 4; k++) {
                longlong2 a = p[2 * k];
                longlong2 b = p[2 * k + 1];
                w[k] = (unsigned)(a.x & 0xFF) | ((unsigned)(a.y & 0xFF) << 8) |
                       ((unsigned)(b.x & 0xFF) << 16) | ((unsigned)(b.y & 0xFF) << 24);
            }
        }
        o.x = w[0]; o.y = w[1]; o.z = w[2]; o.w = w[3];
        ((uint4*)g_labels)[q] = o;
    }
}

// K1: one block per plane. Lane-sliced histogram: cell = hist[key*32 + lane],
// bank == lane for every hot-loop atomic -> guaranteed conflict-free.
// Packed n(16b)|pos(8b)|ign(8b). Cold phase: lane-ROTATED 32-cell merge
// (conflict-free), e-bucket mapping, per-bucket BCE via log1p(sqrt(e/(2-e))),
// suffix scan, exact-integer Jaccard integral, non-spinning ticket combine.
__global__ __launch_bounds__(THREADS, 1) void lovasz_kernel(const float* __restrict__ logits,
                                                            float* __restrict__ out) {
    extern __shared__ unsigned int hist[];            // KB*32 cells
    __shared__ double   wsum[32][2];
    __shared__ double   fin[NBC][2];
    __shared__ unsigned s_rank;

    const int bc   = blockIdx.x;
    const int b    = bc >> 4;
    const int c    = bc & 15;
    const int tid  = threadIdx.x;
    const int lane = tid & 31;

    {   // zero init, 16B stores
        uint4 z4 = make_uint4(0u, 0u, 0u, 0u);
        uint4* h4 = reinterpret_cast<uint4*>(hist);
        for (int j = tid; j < KB * 8; j += THREADS) h4[j] = z4;
    }
    __syncthreads();

    const float4* lg4 = reinterpret_cast<const float4*>(logits + (size_t)bc * HW);
    const uint2*  lb8 = reinterpret_cast<const uint2*>(g_labels + (size_t)b * HW);
    unsigned int* myslot = hist + lane;   // per-lane column; index step = key*32

    #pragma unroll 2
    for (int q = tid; q < HW / 8; q += THREADS) {
        float4 zA = lg4[2 * q];
        float4 zB = lg4[2 * q + 1];
        uint2  lb = lb8[q];
        float zz[8] = { zA.x, zA.y, zA.z, zA.w, zB.x, zB.y, zB.z, zB.w };
        unsigned tw[8];
        #pragma unroll
        for (int j = 0; j < 4; j++) {
            tw[j]     = (lb.x >> (8 * j)) & 0xFFu;
            tw[j + 4] = (lb.y >> (8 * j)) & 0xFFu;
        }
        #pragma unroll
        for (int j = 0; j < 8; j++) {
            float x = fast_tanh(zz[j]);
            int key = (int)fmaf(x, (float)(KB / 2), (float)(KB / 2));
            key = min(max(key, 0), KB - 1);
            unsigned t = tw[j];
            unsigned inc = 1u + ((t == (unsigned)c) ? 0x10000u : 0u)
                              + ((t & 16u) << 20);
            atomicAdd(myslot + (key << 5), inc);
        }
    }
    __syncthreads();

    // Merge 32 lane-cells per bucket, lane-rotated so lane k reads bank (l+k)&31
    // at every step -> conflict-free (the R11 version was 32-way conflicted).
    unsigned vm = 0;
    #pragma unroll
    for (int l = 0; l < 32; l++) {
        int ll = (l + lane) & 31;
        vm += hist[(tid << 5) + ll];      // packed add, fields can't overflow
    }
    __syncthreads();
    hist[tid] = vm;                       // merged hist now in hist[0..KB)
    __syncthreads();

    unsigned long long* sbuf = (unsigned long long*)(hist + 8192);  // past merged region

    // Per-thread e-bucket totals + per-bucket BCE (1 e-bucket per thread).
    const int eb = tid;
    unsigned va = hist[eb];
    unsigned vb = hist[KB - 1 - eb];
    unsigned nA = va & 0xFFFFu;
    unsigned pA = (va >> 16) & 0xFFu;
    unsigned iA = va >> 24;
    unsigned pB = (vb >> 16) & 0xFFu;
    const unsigned n_t = nA - pA + pB;
    const unsigned p_t = pB;
    double bced;
    {
        const float LN2 = 0.6931471805599453f;
        float em = ((float)eb + 0.5f) * (2.0f / (float)KB);
        float s  = sqrtf(em * fast_rcp(2.0f - em));
        float gb = fast_lg2(1.0f + s) * LN2;
        bced = (double)(nA - pA - iA + pB) * (double)gb;
    }
    sbuf[tid] = ((unsigned long long)n_t << 32) | (unsigned long long)p_t;
    __syncthreads();
    // Inclusive SUFFIX scan (descending-error order).
    for (int d = 1; d < THREADS; d <<= 1) {
        unsigned long long v = (tid + d < THREADS) ? sbuf[tid + d] : 0ULL;
        __syncthreads();
        sbuf[tid] += v;
        __syncthreads();
    }
    const unsigned long long tot = sbuf[0];
    const long long P = (long long)(tot & 0xFFFFFFFFULL);
    unsigned long long inc2 = sbuf[tid];
    long long i0 = (long long)(inc2 >> 32) - (long long)n_t;
    long long p0 = (long long)(inc2 & 0xFFFFFFFFULL) - (long long)p_t;

    // Exact integer Jaccard delta for this e-bucket.
    double contrib = 0.0;
    {
        long long p = (long long)pB;
        long long n = (long long)n_t;
        if (n > 0) {
            long long i1 = i0 + n, p1 = p0 + p;
            double dJ;
            if (P > 0) {
                long long A0 = P - p0, B0 = P + i0 - p0;
                long long A1 = P - p1, B1 = P + i1 - p1;
                dJ = (double)(A0 * B1 - A1 * B0) / ((double)B0 * (double)B1);
            } else {
                dJ = (i0 == 0) ? 1.0 : 0.0;
            }
            contrib = ((double)eb + 0.5) * (2.0 / (double)KB) * dJ;
        }
    }

    // Deterministic block reduction.
    const unsigned mask = 0xFFFFFFFFu;
    #pragma unroll
    for (int off = 16; off > 0; off >>= 1) {
        contrib += __shfl_down_sync(mask, contrib, off);
        bced    += __shfl_down_sync(mask, bced, off);
    }
    const int wid = tid >> 5;
    if (lane == 0) { wsum[wid][0] = contrib; wsum[wid][1] = bced; }
    __syncthreads();
    if (wid == 0) {
        double cv = wsum[lane][0];
        double bv = wsum[lane][1];
        #pragma unroll
        for (int off = 16; off > 0; off >>= 1) {
            cv += __shfl_down_sync(mask, cv, off);
            bv += __shfl_down_sync(mask, bv, off);
        }
        if (lane == 0) { g_part[bc * 2 + 0] = cv; g_part[bc * 2 + 1] = bv; }
    }

    // Non-spinning last-arriving-block combine (proven; cannot deadlock).
    __threadfence();
    __syncthreads();
    if (tid == 0) s_rank = atomicAdd(&g_arrive, 1u);
    __syncthreads();
    if (s_rank == NBC - 1) {
        __threadfence();
        if (tid < NBC) {
            fin[tid][0] = __ldcg(&g_part[tid * 2]);
            fin[tid][1] = __ldcg(&g_part[tid * 2 + 1]);
        }
        __syncthreads();
        for (int stride = NBC / 2; stride > 0; stride >>= 1) {
            if (tid < stride) {
                fin[tid][0] += fin[tid + stride][0];
                fin[tid][1] += fin[tid + stride][1];
            }
            __syncthreads();
        }
        if (tid == 0) {
            out[0] = (float)(fin[0][0] * (1.0 / 128.0) + fin[0][1] * (1.0 / 33554432.0));
            g_arrive = 0;
        }
    }
}

extern "C" void kernel_launch(void* const* d_in, const int* in_sizes, int n_in,
                              void* d_out, int out_size) {
    const float* logits;
    const void*  target;
    if (in_sizes[0] == NB * NC * HW) {
        logits = (const float*)d_in[0];
        target = d_in[1];
    } else {
        logits = (const float*)d_in[1];
        target = d_in[0];
    }
    cudaFuncSetAttribute(lovasz_kernel, cudaFuncAttributeMaxDynamicSharedMemorySize, DYN_SMEM);
    prep_kernel<<<(NB * HW / 16 + 1023) / 1024, 1024>>>(target);
    lovasz_kernel<<<NBC, THREADS, DYN_SMEM>>>(logits, (float*)d_out);
}

// round 14
// speedup vs baseline: 1.5031x; 1.0078x over previous
#include <cuda_runtime.h>
#include <cstdint>

#define HW      262144
#define NB      8
#define NC      16
#define NBC     128                // class-planes
#define KB      1024               // buckets over x=tanh(z) in (-1,1)
#define THREADS 1024
#define DYN_SMEM (KB * 32 * 4)     // lane-sliced histogram = 128 KB

// Scratch (no allocations allowed)
__device__ unsigned char g_labels[NB * HW];
__device__ double        g_part[NBC * 2];
__device__ unsigned int  g_arrive;          // zero-init; reset by combiner each call

__device__ __forceinline__ float fast_tanh(float x) { float y; asm("tanh.approx.f32 %0, %1;" : "=f"(y) : "f"(x)); return y; }
__device__ __forceinline__ float fast_lg2(float x)  { float y; asm("lg2.approx.f32 %0, %1;"  : "=f"(y) : "f"(x)); return y; }
__device__ __forceinline__ float fast_rcp(float x)  { float y; asm("rcp.approx.f32 %0, %1;"  : "=f"(y) : "f"(x)); return y; }

// K0: target (int32 or int64) -> uint8, 16 labels per thread. Dtype detected
// per-block: if truly int64 all high words are 0 (labels 0..16).
__global__ __launch_bounds__(1024) void prep_kernel(const void* __restrict__ target) {
    __shared__ int s_is32;
    if (threadIdx.x < 32) {
        const unsigned long long* t64 = (const unsigned long long*)target;
        unsigned hi = (unsigned)(t64[threadIdx.x] >> 32) |
                      (unsigned)(t64[threadIdx.x + 32] >> 32);
        #pragma unroll
        for (int off = 16; off > 0; off >>= 1)
            hi |= __shfl_down_sync(0xFFFFFFFFu, hi, off);
        if (threadIdx.x == 0) s_is32 = (hi != 0);
    }
    __syncthreads();
    const int is32 = s_is32;

    int q = blockIdx.x * blockDim.x + threadIdx.x;   // 16-label group
    if (q < (NB * HW) / 16) {
        uint4 o;
        unsigned w[4];
        if (is32) {
            const int4* p = (const int4*)target + (size_t)q * 4;
            #pragma unroll
            for (int k = 0; k < 4; k++) {
                int4 v = p[k];
                w[k] = (unsigned)v.x | ((unsigned)v.y << 8) |
                       ((unsigned)v.z << 16) | ((unsigned)v.w << 24);
            }
        } else {
            const longlong2* p = (const longlong2*)target + (size_t)q * 8;
            #pragma unroll
            for (int k = 0; k < 4; k++) {
                longlong2 a = p[2 * k];
                longlong2 b = p[2 * k + 1];
                w[k] = (unsigned)(a.x & 0xFF) | ((unsigned)(a.y & 0xFF) << 8) |
                       ((unsigned)(b.x & 0xFF) << 16) | ((unsigned)(b.y & 0xFF) << 24);
            }
        }
        o.x = w[0]; o.y = w[1]; o.z = w[2]; o.w = w[3];
        ((uint4*)g_labels)[q] = o;
    }
}

// K1: one block per plane. Lane-sliced histogram: cell = hist[key*32 + lane],
// bank == lane for every hot-loop atomic -> guaranteed conflict-free.
// inc comes from a 17-entry smem LUT (banks 0..16, duplicates broadcast ->
// conflict-free LDS). Packed n(16b)|pos(8b)|ign(8b). Cold phase: lane-rotated
// conflict-free merge, e-bucket mapping, per-bucket BCE, suffix scan,
// exact-integer Jaccard integral, non-spinning ticket combine.
__global__ __launch_bounds__(THREADS, 1) void lovasz_kernel(const float* __restrict__ logits,
                                                            float* __restrict__ out) {
    extern __shared__ unsigned int hist[];            // KB*32 cells
    __shared__ unsigned inc_tab[32];
    __shared__ double   wsum[32][2];
    __shared__ double   fin[NBC][2];
    __shared__ unsigned s_rank;

    const int bc   = blockIdx.x;
    const int b    = bc >> 4;
    const int c    = bc & 15;
    const int tid  = threadIdx.x;
    const int lane = tid & 31;

    if (tid < 32) {
        unsigned t = (unsigned)tid;
        inc_tab[tid] = 1u + ((t == (unsigned)c) ? 0x10000u : 0u)
                          + ((t == 16u) ? 0x1000000u : 0u);
    }
    {   // zero init, 16B stores
        uint4 z4 = make_uint4(0u, 0u, 0u, 0u);
        uint4* h4 = reinterpret_cast<uint4*>(hist);
        for (int j = tid; j < KB * 8; j += THREADS) h4[j] = z4;
    }
    __syncthreads();

    const float4* lg4 = reinterpret_cast<const float4*>(logits + (size_t)bc * HW);
    const uint2*  lb8 = reinterpret_cast<const uint2*>(g_labels + (size_t)b * HW);
    unsigned int* myslot = hist + lane;   // per-lane column; index step = key*32

    #pragma unroll 2
    for (int q = tid; q < HW / 8; q += THREADS) {
        float4 zA = lg4[2 * q];
        float4 zB = lg4[2 * q + 1];
        uint2  lb = lb8[q];
        float zz[8] = { zA.x, zA.y, zA.z, zA.w, zB.x, zB.y, zB.z, zB.w };
        unsigned iv[8];
        #pragma unroll
        for (int j = 0; j < 4; j++) {
            iv[j]     = inc_tab[(lb.x >> (8 * j)) & 0xFFu];   // conflict-free LDS
            iv[j + 4] = inc_tab[(lb.y >> (8 * j)) & 0xFFu];
        }
        #pragma unroll
        for (int j = 0; j < 8; j++) {
            float x = fast_tanh(zz[j]);
            int key = (int)fmaf(x, (float)(KB / 2), (float)(KB / 2));  // >= 0 since x >= -1
            key = min(key, KB - 1);
            atomicAdd(myslot + (key << 5), iv[j]);
        }
    }
    __syncthreads();

    // Merge 32 lane-cells per bucket, lane-rotated so lane k reads bank (l+k)&31
    // at every step -> conflict-free.
    unsigned vm = 0;
    #pragma unroll
    for (int l = 0; l < 32; l++) {
        int ll = (l + lane) & 31;
        vm += hist[(tid << 5) + ll];      // packed add, fields can't overflow
    }
    __syncthreads();
    hist[tid] = vm;                       // merged hist now in hist[0..KB)
    __syncthreads();

    unsigned long long* sbuf = (unsigned long long*)(hist + 8192);  // past merged region

    // Per-thread e-bucket totals + per-bucket BCE (1 e-bucket per thread).
    const int eb = tid;
    unsigned va = hist[eb];
    unsigned vb = hist[KB - 1 - eb];
    unsigned nA = va & 0xFFFFu;
    unsigned pA = (va >> 16) & 0xFFu;
    unsigned iA = va >> 24;
    unsigned pB = (vb >> 16) & 0xFFu;
    const unsigned n_t = nA - pA + pB;
    const unsigned p_t = pB;
    double bced;
    {
        const float LN2 = 0.6931471805599453f;
        float em = ((float)eb + 0.5f) * (2.0f / (float)KB);
        float s  = sqrtf(em * fast_rcp(2.0f - em));
        float gb = fast_lg2(1.0f + s) * LN2;
        bced = (double)(nA - pA - iA + pB) * (double)gb;
    }
    sbuf[tid] = ((unsigned long long)n_t << 32) | (unsigned long long)p_t;
    __syncthreads();
    // Inclusive SUFFIX scan (descending-error order).
    for (int d = 1; d < THREADS; d <<= 1) {
        unsigned long long v = (tid + d < THREADS) ? sbuf[tid + d] : 0ULL;
        __syncthreads();
        sbuf[tid] += v;
        __syncthreads();
    }
    const unsigned long long tot = sbuf[0];
    const long long P = (long long)(tot & 0xFFFFFFFFULL);
    unsigned long long inc2 = sbuf[tid];
    long long i0 = (long long)(inc2 >> 32) - (long long)n_t;
    long long p0 = (long long)(inc2 & 0xFFFFFFFFULL) - (long long)p_t;

    // Exact integer Jaccard delta for this e-bucket.
    double contrib = 0.0;
    {
        long long p = (long long)pB;
        long long n = (long long)n_t;
        if (n > 0) {
            long long i1 = i0 + n, p1 = p0 + p;
            double dJ;
            if (P > 0) {
                long long A0 = P - p0, B0 = P + i0 - p0;
                long long A1 = P - p1, B1 = P + i1 - p1;
                dJ = (double)(A0 * B1 - A1 * B0) / ((double)B0 * (double)B1);
            } else {
                dJ = (i0 == 0) ? 1.0 : 0.0;
            }
            contrib = ((double)eb + 0.5) * (2.0 / (double)KB) * dJ;
        }
    }

    // Deterministic block reduction.
    const unsigned mask = 0xFFFFFFFFu;
    #pragma unroll
    for (int off = 16; off > 0; off >>= 1) {
        contrib += __shfl_down_sync(mask, contrib, off);
        bced    += __shfl_down_sync(mask, bced, off);
    }
    const int wid = tid >> 5;
    if (lane == 0) { wsum[wid][0] = contrib; wsum[wid][1] = bced; }
    __syncthreads();
    if (wid == 0) {
        double cv = wsum[lane][0];
        double bv = wsum[lane][1];
        #pragma unroll
        for (int off = 16; off > 0; off >>= 1) {
            cv += __shfl_down_sync(mask, cv, off);
            bv += __shfl_down_sync(mask, bv, off);
        }
        if (lane == 0) { g_part[bc * 2 + 0] = cv; g_part[bc * 2 + 1] = bv; }
    }

    // Non-spinning last-arriving-block combine (proven; cannot deadlock).
    __threadfence();
    __syncthreads();
    if (tid == 0) s_rank = atomicAdd(&g_arrive, 1u);
    __syncthreads();
    if (s_rank == NBC - 1) {
        __threadfence();
        if (tid < NBC) {
            fin[tid][0] = __ldcg(&g_part[tid * 2]);
            fin[tid][1] = __ldcg(&g_part[tid * 2 + 1]);
        }
        __syncthreads();
        for (int stride = NBC / 2; stride > 0; stride >>= 1) {
            if (tid < stride) {
                fin[tid][0] += fin[tid + stride][0];
                fin[tid][1] += fin[tid + stride][1];
            }
            __syncthreads();
        }
        if (tid == 0) {
            out[0] = (float)(fin[0][0] * (1.0 / 128.0) + fin[0][1] * (1.0 / 33554432.0));
            g_arrive = 0;
        }
    }
}

extern "C" void kernel_launch(void* const* d_in, const int* in_sizes, int n_in,
                              void* d_out, int out_size) {
    const float* logits;
    const void*  target;
    if (in_sizes[0] == NB * NC * HW) {
        logits = (const float*)d_in[0];
        target = d_in[1];
    } else {
        logits = (const float*)d_in[1];
        target = d_in[0];
    }
    cudaFuncSetAttribute(lovasz_kernel, cudaFuncAttributeMaxDynamicSharedMemorySize, DYN_SMEM);
    prep_kernel<<<(NB * HW / 16 + 1023) / 1024, 1024>>>(target);
    lovasz_kernel<<<NBC, THREADS, DYN_SMEM>>>(logits, (float*)d_out);
}

// round 16
// speedup vs baseline: 1.5809x; 1.0518x over previous
#include <cuda_runtime.h>
#include <cstdint>

#define HW      262144
#define NB      8
#define NC      16
#define NBC     128                // class-planes
#define KB      512                // buckets over x=tanh(z) in (-1,1)
#define THREADS 1024
#define HALF    (HW / 2)
#define DYN_SMEM (KB * 32 * 4)     // lane-sliced histogram = 64 KB -> 2 blocks/SM

// Scratch (no allocations allowed)
__device__ unsigned char g_labels[NB * HW];
__device__ unsigned int  g_hist[NBC][KB];   // per-plane merged hist (zeroed in prep)
__device__ double        g_part[NBC * 2];
__device__ unsigned int  g_arrive;          // zero-init; reset by combiner each call

__device__ __forceinline__ float fast_tanh(float x) { float y; asm("tanh.approx.f32 %0, %1;" : "=f"(y) : "f"(x)); return y; }
__device__ __forceinline__ float fast_lg2(float x)  { float y; asm("lg2.approx.f32 %0, %1;"  : "=f"(y) : "f"(x)); return y; }
__device__ __forceinline__ float fast_rcp(float x)  { float y; asm("rcp.approx.f32 %0, %1;"  : "=f"(y) : "f"(x)); return y; }

// K0: target (int32 or int64) -> uint8, 16 labels per thread; also zeroes g_hist.
__global__ __launch_bounds__(1024) void prep_kernel(const void* __restrict__ target) {
    __shared__ int s_is32;
    if (threadIdx.x < 32) {                           // full warp 0 -> legal shfl
        const unsigned long long* t64 = (const unsigned long long*)target;
        unsigned hi = (unsigned)(t64[threadIdx.x] >> 32) |
                      (unsigned)(t64[threadIdx.x + 32] >> 32);
        #pragma unroll
        for (int off = 16; off > 0; off >>= 1)
            hi |= __shfl_down_sync(0xFFFFFFFFu, hi, off);
        if (threadIdx.x == 0) s_is32 = (hi != 0);
    }
    __syncthreads();
    const int is32 = s_is32;

    int gid = blockIdx.x * blockDim.x + threadIdx.x;
    if (gid < NBC * KB) ((unsigned*)g_hist)[gid] = 0u;   // zero merged hist each call

    int q = gid;                                          // 16-label group
    if (q < (NB * HW) / 16) {
        uint4 o;
        unsigned w[4];
        if (is32) {
            const int4* p = (const int4*)target + (size_t)q * 4;
            #pragma unroll
            for (int k = 0; k < 4; k++) {
                int4 v = p[k];
                w[k] = (unsigned)v.x | ((unsigned)v.y << 8) |
                       ((unsigned)v.z << 16) | ((unsigned)v.w << 24);
            }
        } else {
            const longlong2* p = (const longlong2*)target + (size_t)q * 8;
            #pragma unroll
            for (int k = 0; k < 4; k++) {
                longlong2 a = p[2 * k];
                longlong2 b = p[2 * k + 1];
                w[k] = (unsigned)(a.x & 0xFF) | ((unsigned)(a.y & 0xFF) << 8) |
                       ((unsigned)(b.x & 0xFF) << 16) | ((unsigned)(b.y & 0xFF) << 24);
            }
        }
        o.x = w[0]; o.y = w[1]; o.z = w[2]; o.w = w[3];
        ((uint4*)g_labels)[q] = o;
    }
}

// K1: 256 half-plane blocks (plane = bid&127, half = bid>>7), 2 blocks/SM ->
// 100% occupancy. Lane-sliced conflict-free smem atomics; packed
// n(16b)|pos(8b)|ign(8b); lane-rotated conflict-free merge; halves combine via
// global packed atomicAdd (commutative integer sum -> deterministic).
__global__ __launch_bounds__(THREADS, 2) void hist_kernel(const float* __restrict__ logits) {
    extern __shared__ unsigned int hist[];            // KB*32 cells
    const int bid  = blockIdx.x;
    const int bc   = bid & (NBC - 1);
    const int half = bid >> 7;
    const int b    = bc >> 4;
    const int c    = bc & 15;
    const int tid  = threadIdx.x;
    const int lane = tid & 31;

    {   // zero init, 16B stores
        uint4 z4 = make_uint4(0u, 0u, 0u, 0u);
        uint4* h4 = reinterpret_cast<uint4*>(hist);
        for (int j = tid; j < KB * 8; j += THREADS) h4[j] = z4;
    }
    __syncthreads();

    const float4*   lg4 = reinterpret_cast<const float4*>(logits + (size_t)bc * HW + (size_t)half * HALF);
    const unsigned* lb4 = reinterpret_cast<const unsigned*>(g_labels + (size_t)b * HW + (size_t)half * HALF);
    unsigned int* myslot = hist + lane;   // per-lane column; index step = key*32

    #pragma unroll 4
    for (int q = tid; q < HALF / 4; q += THREADS) {
        float4   z4 = lg4[q];
        unsigned lb = lb4[q];
        float zz[4] = { z4.x, z4.y, z4.z, z4.w };
        #pragma unroll
        for (int j = 0; j < 4; j++) {
            float x = fast_tanh(zz[j]);
            int key = (int)fmaf(x, (float)(KB / 2), (float)(KB / 2));  // >=0 since x>=-1
            key = min(key, KB - 1);
            unsigned t = (lb >> (8 * j)) & 0xFFu;
            unsigned inc = 1u + ((t == (unsigned)c) ? 0x10000u : 0u)
                              + ((t & 16u) << 20);
            atomicAdd(myslot + (key << 5), inc);
        }
    }
    __syncthreads();

    // Lane-rotated conflict-free merge of 32 lane-cells, then global packed add.
    if (tid < KB) {
        unsigned vm = 0;
        #pragma unroll
        for (int l = 0; l < 32; l++) {
            int ll = (l + lane) & 31;
            vm += hist[(tid << 5) + ll];  // packed add, fields can't overflow
        }
        atomicAdd(&g_hist[bc][tid], vm);
    }
}

// K2: 128 blocks x 512 threads, one plane each. e-bucket mapping (neg at j:
// e=1+x_j; pos mirrored at KB-1-j: e=1-x_j), per-bucket BCE via
// log1p(sqrt(e/(2-e))), suffix scan, exact-integer Jaccard integral,
// non-spinning ticket combine. ALL shfls are full-warp (legal masks).
__global__ __launch_bounds__(KB) void scan_kernel(float* __restrict__ out) {
    __shared__ unsigned int       hist[KB];
    __shared__ unsigned long long sbuf[KB];
    __shared__ double             wsum[KB / 32][2];
    __shared__ double             fin[NBC][2];
    __shared__ unsigned           s_rank;

    const int bc   = blockIdx.x;
    const int tid  = threadIdx.x;
    const int lane = tid & 31;

    hist[tid] = __ldcg(&g_hist[bc][tid]);
    __syncthreads();

    // Per-thread e-bucket totals + per-bucket BCE (1 e-bucket per thread).
    const int eb = tid;
    unsigned va = hist[eb];
    unsigned vb = hist[KB - 1 - eb];
    unsigned nA = va & 0xFFFFu;
    unsigned pA = (va >> 16) & 0xFFu;
    unsigned iA = va >> 24;
    unsigned pB = (vb >> 16) & 0xFFu;
    const unsigned n_t = nA - pA + pB;
    const unsigned p_t = pB;
    double bced;
    {
        const float LN2 = 0.6931471805599453f;
        float em = ((float)eb + 0.5f) * (2.0f / (float)KB);
        float s  = sqrtf(em * fast_rcp(2.0f - em));
        float gb = fast_lg2(1.0f + s) * LN2;
        bced = (double)(nA - pA - iA + pB) * (double)gb;
    }
    sbuf[tid] = ((unsigned long long)n_t << 32) | (unsigned long long)p_t;
    __syncthreads();
    // Inclusive SUFFIX scan (descending-error order).
    for (int d = 1; d < KB; d <<= 1) {
        unsigned long long v = (tid + d < KB) ? sbuf[tid + d] : 0ULL;
        __syncthreads();
        sbuf[tid] += v;
        __syncthreads();
    }
    const unsigned long long tot = sbuf[0];
    const long long P = (long long)(tot & 0xFFFFFFFFULL);
    unsigned long long inc2 = sbuf[tid];
    long long i0 = (long long)(inc2 >> 32) - (long long)n_t;
    long long p0 = (long long)(inc2 & 0xFFFFFFFFULL) - (long long)p_t;

    // Exact integer Jaccard delta for this e-bucket.
    double contrib = 0.0;
    {
        long long p = (long long)pB;
        long long n = (long long)n_t;
        if (n > 0) {
            long long i1 = i0 + n, p1 = p0 + p;
            double dJ;
            if (P > 0) {
                long long A0 = P - p0, B0 = P + i0 - p0;
                long long A1 = P - p1, B1 = P + i1 - p1;
                dJ = (double)(A0 * B1 - A1 * B0) / ((double)B0 * (double)B1);
            } else {
                dJ = (i0 == 0) ? 1.0 : 0.0;
            }
            contrib = ((double)eb + 0.5) * (2.0 / (double)KB) * dJ;
        }
    }

    // Deterministic block reduction. Stage 1: every warp, full 32 lanes.
    const unsigned mask = 0xFFFFFFFFu;
    double bv0 = bced;
    #pragma unroll
    for (int off = 16; off > 0; off >>= 1) {
        contrib += __shfl_down_sync(mask, contrib, off);
        bv0     += __shfl_down_sync(mask, bv0, off);
    }
    const int wid = tid >> 5;
    if (lane == 0) { wsum[wid][0] = contrib; wsum[wid][1] = bv0; }
    __syncthreads();
    // Stage 2: warp 0, ALL 32 lanes execute the shfl (legal); lanes >= KB/32 add 0.
    if (wid == 0) {
        double cv = (lane < KB / 32) ? wsum[lane][0] : 0.0;
        double bv = (lane < KB / 32) ? wsum[lane][1] : 0.0;
        #pragma unroll
        for (int off = 16; off > 0; off >>= 1) {
            cv += __shfl_down_sync(mask, cv, off);
            bv += __shfl_down_sync(mask, bv, off);
        }
        if (lane == 0) { g_part[bc * 2 + 0] = cv; g_part[bc * 2 + 1] = bv; }
    }

    // Non-spinning last-arriving-block combine (ticket; cannot deadlock).
    __threadfence();
    __syncthreads();
    if (tid == 0) s_rank = atomicAdd(&g_arrive, 1u);
    __syncthreads();
    if (s_rank == NBC - 1) {
        __threadfence();
        if (tid < NBC) {
            fin[tid][0] = __ldcg(&g_part[tid * 2]);
            fin[tid][1] = __ldcg(&g_part[tid * 2 + 1]);
        }
        __syncthreads();
        for (int stride = NBC / 2; stride > 0; stride >>= 1) {
            if (tid < stride) {
                fin[tid][0] += fin[tid + stride][0];
                fin[tid][1] += fin[tid + stride][1];
            }
            __syncthreads();
        }
        if (tid == 0) {
            out[0] = (float)(fin[0][0] * (1.0 / 128.0) + fin[0][1] * (1.0 / 33554432.0));
            g_arrive = 0;
        }
    }
}

extern "C" void kernel_launch(void* const* d_in, const int* in_sizes, int n_in,
                              void* d_out, int out_size) {
    const float* logits;
    const void*  target;
    if (in_sizes[0] == NB * NC * HW) {
        logits = (const float*)d_in[0];
        target = d_in[1];
    } else {
        logits = (const float*)d_in[1];
        target = d_in[0];
    }
    cudaFuncSetAttribute(hist_kernel, cudaFuncAttributeMaxDynamicSharedMemorySize, DYN_SMEM);
    prep_kernel<<<(NB * HW / 16 + 1023) / 1024, 1024>>>(target);
    hist_kernel<<<2 * NBC, THREADS, DYN_SMEM>>>(logits);
    scan_kernel<<<NBC, KB>>>((float*)d_out);
}